// round 13
// baseline (speedup 1.0000x reference)
#include <cuda_runtime.h>

#define T_STEPS 256
#define NPRE    1024
#define NPOST   1024
#define K       16            // 2^-16 rel truncation; measured rel_err 3.2e-5, 30x under 1e-3

// Scratch vectors (no allocations allowed)
__device__ float g_x[NPRE];   // pre trace at T
__device__ float g_p[NPRE];   // pre[T-1][:]
__device__ float g_y[NPOST];  // post trace at T
__device__ float g_q[NPOST];  // post[T-1][:]

// Kernel A: closed-form traces, computed ONCE.
// x[i] = sum_{k=0..K-1} pre[T-K+k][i] * 2^(k-K)   (TP=TN=2 geometric filters; TE=1
// wipes e history so only the last outer-product term survives)
__global__ void trace_kernel(const float* __restrict__ pre,
                             const float* __restrict__ post) {
    const int t     = blockIdx.x * blockDim.x + threadIdx.x;  // 0..2047
    const int which = t >> 10;                                // 0 = pre, 1 = post
    const int col   = t & 1023;

    const float* __restrict__ s = which ? post : pre;
    const float* __restrict__ b = s + (size_t)(T_STEPS - K) * NPRE + col;

    // 16 independent loads (MLP=16, single latency exposure), 2 acc chains
    float a0 = 0.0f, a1 = 0.0f, last = 0.0f;
    #pragma unroll
    for (int k = 0; k < K; k += 2) {
        const float v0 = b[(size_t)(k + 0) * NPRE];
        const float v1 = b[(size_t)(k + 1) * NPRE];
        a0 = fmaf(v0, __uint_as_float((unsigned)(127 - K + k + 0) << 23), a0);
        a1 = fmaf(v1, __uint_as_float((unsigned)(127 - K + k + 1) << 23), a1);
        last = v1;                                            // k+1 == K-1 survives
    }
    const float acc = a0 + a1;

    if (which) { g_y[col] = acc; g_q[col] = last; }
    else       { g_x[col] = acc; g_p[col] = last; }

    // Release the PDL-dependent outer kernel as early as legal.
    cudaTriggerProgrammaticLaunchCompletion();
}

// Kernel B: e[i][j] = x[i]*q[j] - p[i]*y[j].
// Launched with ProgrammaticStreamSerialization: CTAs ramp up (dispatch, regs,
// index math) concurrently with trace_kernel, then block at the grid-dependency
// sync just before the first trace-dependent load.
__global__ __launch_bounds__(1024, 2)
void outer_kernel(float* __restrict__ e) {
    const int tid  = threadIdx.x;
    const int col4 = tid & 255;
    const int i    = blockIdx.x * 4 + (tid >> 8);

    // Compute all trace-independent state before the dependency sync.
    float4* __restrict__ out4 =
        reinterpret_cast<float4*>(e) + (size_t)i * (NPOST / 4) + col4;

    cudaGridDependencySynchronize();   // wait for trace_kernel's stores

    const float xi = g_x[i];                                  // warp-broadcast load
    const float pi = g_p[i];
    const float4 y4 = reinterpret_cast<const float4*>(g_y)[col4];
    const float4 q4 = reinterpret_cast<const float4*>(g_q)[col4];

    float4 o;
    o.x = fmaf(xi, q4.x, -pi * y4.x);
    o.y = fmaf(xi, q4.y, -pi * y4.y);
    o.z = fmaf(xi, q4.z, -pi * y4.z);
    o.w = fmaf(xi, q4.w, -pi * y4.w);
    *out4 = o;
}

extern "C" void kernel_launch(void* const* d_in, const int* in_sizes, int n_in,
                              void* d_out, int out_size) {
    const float* pre  = (const float*)d_in[0];   // [T, NPRE]
    const float* post = (const float*)d_in[1];   // [T, NPOST]
    float* e = (float*)d_out;                    // [NPRE, NPOST]

    trace_kernel<<<8, 256>>>(pre, post);

    // Outer kernel with Programmatic Dependent Launch on the same (captured) stream.
    cudaLaunchConfig_t cfg = {};
    cfg.gridDim  = dim3(NPRE / 4, 1, 1);         // 256 CTAs
    cfg.blockDim = dim3(1024, 1, 1);
    cfg.dynamicSmemBytes = 0;
    cfg.stream = 0;                              // legacy default stream (captured)

    cudaLaunchAttribute attr[1];
    attr[0].id = cudaLaunchAttributeProgrammaticStreamSerialization;
    attr[0].val.programmaticStreamSerializationAllowed = 1;
    cfg.attrs = attr;
    cfg.numAttrs = 1;

    cudaLaunchKernelEx(&cfg, outer_kernel, e);
}